// round 15
// baseline (speedup 1.0000x reference)
#include <cuda_runtime.h>
#include <cuda_bf16.h>
#include <stdint.h>

#define N_POINTS  1048576
#define DD        64
#define NUM_BINS  (DD*DD*DD)         // 262144
#define LL        128
#define TT        8
#define CAP       8
#define STORE_CAP 32
#define OVF_CAP   4096

#define LAT_ELEMS  (LL*LL*LL*TT)     // 16777216
#define BUF_ELEMS  (NUM_BINS*CAP*3)
#define PLANE      (LL*LL*LL)        // 2097152 (output cells)

// padded scratch geometry: x,y pad 1 each side; z pad 4 each side (16B align)
#define ZP      136                  // padded z row (floats)
#define YP      130
#define XP      130
#define SLAB    (YP*ZP)              // 17680 floats per x-slab
#define TPLANE  (XP*SLAB)            // 2298400 floats per type
#define SCR_TOTAL (TT*TPLANE)        // 18387200 floats (73.5 MB)
#define SCR_F4   (SCR_TOTAL/4)       // 4596800

// grids
#define BIN_BLOCKS   (N_POINTS/256)               // 4096
#define ZERO_BLOCKS  ((SCR_F4 + 255)/256)         // 17957
#define A_BLOCKS     (BIN_BLOCKS + ZERO_BLOCKS)
#define SPLAT_BLOCKS (NUM_BINS*4/256)             // 4096 (4 slots/bin)
#define FILL_BLOCKS  (NUM_BINS/256)               // 1024
#define C_BLOCKS     (FILL_BLOCKS*9)              // 9216 (8 tr + 1 fill per group)

__device__ int    g_count[NUM_BINS];
__device__ int    g_ovf_count;
__device__ __align__(16)  float4 g_ovf[OVF_CAP];
__device__ __align__(16)  float4 g_pts[NUM_BINS * STORE_CAP]; // (x,y,z,(idx<<3)|t)
__device__ __align__(128) float  g_scr[SCR_TOTAL];            // padded [t][x][y][z]

// ---- vector reductions ------------------------------------------------------
__device__ __forceinline__ void red4(float* p, float a, float b, float c, float d) {
    asm volatile("red.global.add.v4.f32 [%0], {%1,%2,%3,%4};"
                 :: "l"(p), "f"(a), "f"(b), "f"(c), "f"(d) : "memory");
}
__device__ __forceinline__ void red2(float* p, float a, float b) {
    asm volatile("red.global.add.v2.f32 [%0], {%1,%2};"
                 :: "l"(p), "f"(a), "f"(b) : "memory");
}

// ---- uniform branch-free splat (guard-band padding absorbs boundaries) -----
__device__ __forceinline__ void splat_point(float px, float py, float pz, int t)
{
    int cx = (int)floorf(px * 4.0f);
    int cy = (int)floorf(py * 4.0f);
    int cz = (int)floorf(pz * 4.0f);

    const float inv = 1.0f / (2.0f * 0.3f * 0.3f);
    float ex[3], ey[3], ez[3];
    #pragma unroll
    for (int o = 0; o < 3; o++) {
        int xo = cx + o - 1, yo = cy + o - 1, zo = cz + o - 1;
        float vx = px - ((float)xo + 0.5f) * 0.25f;
        float vy = py - ((float)yo + 0.5f) * 0.25f;
        float vz = pz - ((float)zo + 0.5f) * 0.25f;
        ex[o] = ((unsigned)xo < (unsigned)LL) ? __expf(-vx * vx * inv) : 0.0f;
        ey[o] = ((unsigned)yo < (unsigned)LL) ? __expf(-vy * vy * inv) : 0.0f;
        ez[o] = ((unsigned)zo < (unsigned)LL) ? __expf(-vz * vz * inv) : 0.0f;
    }

    int zbp = cz + 3;        // padded z of window start (cz-1, +4 pad)
    int a   = zbp & 3;

    // shifted ez pattern over 6 cells: u[a..a+2] = ez[0..2]
    float u[6];
    #pragma unroll
    for (int q = 0; q < 6; q++) {
        int d = q - a;
        u[q] = (d == 0) ? ez[0] : (d == 1) ? ez[1] : (d == 2) ? ez[2] : 0.0f;
    }
    bool two = (a >= 2);

    // padded base: xp = cx (=cx-1+1), yp = cy, z quad start = zbp - a
    float* base = g_scr + (size_t)t * TPLANE
                + (size_t)cx * SLAB + (size_t)cy * ZP + (zbp - a);

    #pragma unroll
    for (int ix = 0; ix < 3; ix++) {
        #pragma unroll
        for (int iy = 0; iy < 3; iy++) {
            float w = ex[ix] * ey[iy];
            float* p = base + ix * SLAB + iy * ZP;
            red4(p, w*u[0], w*u[1], w*u[2], w*u[3]);
            if (two)
                red2(p + 4, w*u[4], w*u[5]);
        }
    }
}

// ---------------------------------------------------------------------------
// Kernel A: [bin blocks first | zero blocks last]. Zero blocks run at the
// kernel tail -> scratch zeros are the freshest L2 lines when splat starts.
// ---------------------------------------------------------------------------
__global__ void __launch_bounds__(256)
bin_zero_kernel(const float* __restrict__ pts,
                const int* __restrict__ mask,
                const int* __restrict__ types)
{
    int g = blockIdx.x;

    if (g >= BIN_BLOCKS) {
        int zid = (g - BIN_BLOCKS) * 256 + threadIdx.x;
        if (zid < SCR_F4)
            ((float4*)g_scr)[zid] = make_float4(0.f, 0.f, 0.f, 0.f);
        return;
    }

    int i = g * 256 + threadIdx.x;
    if (!mask[i]) return;

    float px = pts[3*i + 0];
    float py = pts[3*i + 1];
    float pz = pts[3*i + 2];
    int   t  = types[i];

    int bx = min(max((int)floorf(px * 2.0f), 0), DD - 1);
    int by = min(max((int)floorf(py * 2.0f), 0), DD - 1);
    int bz = min(max((int)floorf(pz * 2.0f), 0), DD - 1);
    int bin = (bx * DD + by) * DD + bz;
    int pos = atomicAdd(&g_count[bin], 1);
    if (pos < STORE_CAP) {
        g_pts[bin * STORE_CAP + pos] =
            make_float4(px, py, pz, __int_as_float((i << 3) | t));
    } else {
        // P ~ 1e-22: park in overflow list; drained in splat_kernel after
        // zeroing is complete (no race with zero blocks).
        int op = atomicAdd(&g_ovf_count, 1);
        if (op < OVF_CAP)
            g_ovf[op] = make_float4(px, py, pz, __int_as_float((i << 3) | t));
    }
}

// ---------------------------------------------------------------------------
// Kernel B: splat (bin = tid/4, slot = tid%4) — fully uniform fast path.
// ---------------------------------------------------------------------------
__global__ void __launch_bounds__(256)
splat_kernel()
{
    int tid = blockIdx.x * 256 + threadIdx.x;
    int bin  = tid >> 2;
    int slot = tid & 3;

    // overflow drain (normally zero entries)
    if (blockIdx.x == 0) {
        int n = min(g_ovf_count, OVF_CAP);
        for (int e = threadIdx.x; e < n; e += 256) {
            float4 r = g_ovf[e];
            splat_point(r.x, r.y, r.z, __float_as_int(r.w) & 7);
        }
    }

    int m = min(g_count[bin], STORE_CAP);
    for (int s = slot; s < m; s += 4) {
        float4 r = g_pts[bin * STORE_CAP + s];
        splat_point(r.x, r.y, r.z, __float_as_int(r.w) & 7);
    }
}

// ---------------------------------------------------------------------------
// transpose work for one block: padded [t][x][y][z] -> [x][y][z][t]
// ---------------------------------------------------------------------------
__device__ __forceinline__ void do_transpose(int tb, float* __restrict__ lat)
{
    int v = tb * 256 + threadIdx.x;     // (x*128+y)*128+z
    int x = v >> 14;
    int rem = v & 16383;
    int y = rem >> 7;
    int z = rem & 127;

    size_t base = (size_t)(x + 1) * SLAB + (size_t)(y + 1) * ZP + (z + 4);

    float o[TT];
    #pragma unroll
    for (int t = 0; t < TT; t++)
        o[t] = g_scr[(size_t)t * TPLANE + base];

    float4* out = (float4*)(lat + (size_t)v * TT);
    out[0] = make_float4(o[0], o[1], o[2], o[3]);
    out[1] = make_float4(o[4], o[5], o[6], o[7]);
}

// ---------------------------------------------------------------------------
// fill work for one block (one bin per thread).
// ---------------------------------------------------------------------------
__device__ __forceinline__ void do_fill(int fb,
                                        float* __restrict__ buf,
                                        float* __restrict__ bmask)
{
    int b = fb * 256 + threadIdx.x;

    const float4* rec = &g_pts[(size_t)b * STORE_CAP];

    float w8[CAP];
    #pragma unroll
    for (int e = 0; e < CAP; e++) w8[e] = rec[e].w;

    int cnt = g_count[b];
    int m = min(cnt, STORE_CAP);

    int key[CAP];
    #pragma unroll
    for (int s = 0; s < CAP; s++) key[s] = 0x7FFFFFFF;

    #pragma unroll
    for (int e = 0; e < CAP; e++) {
        if (e >= m) break;
        int k = (__float_as_int(w8[e]) << 5) | e;
        #pragma unroll
        for (int j = 0; j < CAP; j++) {
            int lo = min(k, key[j]);
            int hi = max(k, key[j]);
            key[j] = lo;
            k = hi;
        }
    }
    for (int e = CAP; e < m; e++) {
        int k = (__float_as_int(rec[e].w) << 5) | e;
        #pragma unroll
        for (int j = 0; j < CAP; j++) {
            int lo = min(k, key[j]);
            int hi = max(k, key[j]);
            key[j] = lo;
            k = hi;
        }
    }

    int nval = min(cnt, CAP);
    float o[CAP * 3];
    float mk[CAP];
    #pragma unroll
    for (int s = 0; s < CAP; s++) {
        float x = 0.f, y = 0.f, z = 0.f, mv = 0.f;
        if (s < nval) {
            float4 r = rec[key[s] & (STORE_CAP - 1)];
            x = r.x; y = r.y; z = r.z; mv = 1.0f;
        }
        o[3*s + 0] = x; o[3*s + 1] = y; o[3*s + 2] = z;
        mk[s] = mv;
    }

    float4* bp = (float4*)(buf + (size_t)b * (CAP * 3));
    #pragma unroll
    for (int q = 0; q < 6; q++)
        bp[q] = make_float4(o[4*q + 0], o[4*q + 1], o[4*q + 2], o[4*q + 3]);

    float4* mp = (float4*)(bmask + (size_t)b * CAP);
    mp[0] = make_float4(mk[0], mk[1], mk[2], mk[3]);
    mp[1] = make_float4(mk[4], mk[5], mk[6], mk[7]);
}

// ---------------------------------------------------------------------------
// Kernel C: interleaved [transpose | fill]. Groups of 9: r<8 transpose, r==8 fill.
// ---------------------------------------------------------------------------
__global__ void __launch_bounds__(256)
transpose_fill_kernel(float* __restrict__ lat,
                      float* __restrict__ buf,
                      float* __restrict__ bmask)
{
    int g = blockIdx.x;
    int k = g / 9;
    int r = g - k * 9;
    if (r < 8) do_transpose(k * 8 + r, lat);
    else       do_fill(k, buf, bmask);
}

// ---------------------------------------------------------------------------
extern "C" void kernel_launch(void* const* d_in, const int* in_sizes, int n_in,
                              void* d_out, int out_size)
{
    const float* points = (const float*)d_in[0];
    const int*   mask   = (const int*)d_in[1];
    const int*   types  = (const int*)d_in[2];

    float* out   = (float*)d_out;
    float* lat   = out;                       // [128,128,128,8]
    float* buf   = out + LAT_ELEMS;           // [262144,8,3]
    float* bmask = buf + BUF_ELEMS;           // [262144,8]

    void* cptr = nullptr;
    cudaGetSymbolAddress(&cptr, g_count);
    cudaMemsetAsync(cptr, 0, (size_t)NUM_BINS * sizeof(int), 0);
    void* optr = nullptr;
    cudaGetSymbolAddress(&optr, g_ovf_count);
    cudaMemsetAsync(optr, 0, sizeof(int), 0);

    bin_zero_kernel<<<A_BLOCKS, 256>>>(points, mask, types);
    splat_kernel<<<SPLAT_BLOCKS, 256>>>();
    transpose_fill_kernel<<<C_BLOCKS, 256>>>(lat, buf, bmask);
}

// round 17
// speedup vs baseline: 1.0690x; 1.0690x over previous
#include <cuda_runtime.h>
#include <cuda_bf16.h>
#include <stdint.h>

#define N_POINTS  1048576
#define DD        64
#define NUM_BINS  (DD*DD*DD)         // 262144
#define LL        128
#define TT        8
#define CAP       8
#define STORE_CAP 32
#define OVF_CAP   4096

#define LAT_ELEMS  (LL*LL*LL*TT)     // 16777216
#define BUF_ELEMS  (NUM_BINS*CAP*3)
#define PLANE      (LL*LL*LL)        // 2097152 output cells

// scratch: per type, x in [-1,128] (XP=130), (y,z) padded to [-2,129] and
// packed as 2x2 quads: 66x66 quad grid, 4 floats per quad (16B aligned).
#define YQ      66
#define ZQ      66
#define SLAB    (YQ*ZQ*4)            // 17424 floats per x-slab
#define XP      130
#define TPLANE  (XP*SLAB)            // 2265120 floats per type
#define SCR_TOTAL (TT*TPLANE)        // 18120960 floats (72.5 MB)
#define SCR_F4   (SCR_TOTAL/4)       // 4530240

// grids
#define BIN_BLOCKS   (N_POINTS/256)               // 4096
#define ZERO_BLOCKS  ((SCR_F4 + 255)/256)         // 17697
#define A_BLOCKS     (BIN_BLOCKS + ZERO_BLOCKS)
#define SPLAT_BLOCKS (NUM_BINS*4/256)             // 4096 (4 slots/bin)
#define FILL_BLOCKS  (NUM_BINS/256)               // 1024
#define C_BLOCKS     (FILL_BLOCKS*3)              // 3072, groups of 3 (2 tr + 1 fill)

__device__ int    g_count[NUM_BINS];
__device__ int    g_ovf_count;
__device__ __align__(16)  float4 g_ovf[OVF_CAP];
__device__ __align__(16)  float4 g_pts[NUM_BINS * STORE_CAP]; // (x,y,z,(idx<<3)|t)
__device__ __align__(128) float  g_scr[SCR_TOTAL];

// ---- vector reduction ------------------------------------------------------
__device__ __forceinline__ void red4(float* p, float a, float b, float c, float d) {
    asm volatile("red.global.add.v4.f32 [%0], {%1,%2,%3,%4};"
                 :: "l"(p), "f"(a), "f"(b), "f"(c), "f"(d) : "memory");
}

// ---- uniform branch-free splat: 12 red4 into (y,z)-paired quads ------------
__device__ __forceinline__ void splat_point(float px, float py, float pz, int t)
{
    int cx = (int)floorf(px * 4.0f);
    int cy = (int)floorf(py * 4.0f);
    int cz = (int)floorf(pz * 4.0f);

    const float inv = 1.0f / (2.0f * 0.3f * 0.3f);
    float ex[3], ey[3], ez[3];
    #pragma unroll
    for (int o = 0; o < 3; o++) {
        int xo = cx + o - 1, yo = cy + o - 1, zo = cz + o - 1;
        float vx = px - ((float)xo + 0.5f) * 0.25f;
        float vy = py - ((float)yo + 0.5f) * 0.25f;
        float vz = pz - ((float)zo + 0.5f) * 0.25f;
        ex[o] = ((unsigned)xo < (unsigned)LL) ? __expf(-vx * vx * inv) : 0.0f;
        ey[o] = ((unsigned)yo < (unsigned)LL) ? __expf(-vy * vy * inv) : 0.0f;
        ez[o] = ((unsigned)zo < (unsigned)LL) ? __expf(-vz * vz * inv) : 0.0f;
    }

    // padded coords of window start: ypad = (cy-1)+2, zpad = (cz-1)+2
    int ypad = cy + 1, zpad = cz + 1;
    int ay = ypad & 1, qy0 = ypad >> 1;
    int az = zpad & 1, qz0 = zpad >> 1;

    // shifted weights over the 4 cells covered by 2 quad-rows/cols
    float vy0 = ay ? 0.f   : ey[0];
    float vy1 = ay ? ey[0] : ey[1];
    float vy2 = ay ? ey[1] : ey[2];
    float vy3 = ay ? ey[2] : 0.f;
    float vz0 = az ? 0.f   : ez[0];
    float vz1 = az ? ez[0] : ez[1];
    float vz2 = az ? ez[1] : ez[2];
    float vz3 = az ? ez[2] : 0.f;

    // outer products
    float p00 = vy0*vz0, p01 = vy0*vz1, p02 = vy0*vz2, p03 = vy0*vz3;
    float p10 = vy1*vz0, p11 = vy1*vz1, p12 = vy1*vz2, p13 = vy1*vz3;
    float p20 = vy2*vz0, p21 = vy2*vz1, p22 = vy2*vz2, p23 = vy2*vz3;
    float p30 = vy3*vz0, p31 = vy3*vz1, p32 = vy3*vz2, p33 = vy3*vz3;

    // base quad (qy0, qz0) at x-slab (cx-1)+1 = cx
    float* base = g_scr + (size_t)t * TPLANE + (size_t)cx * SLAB
                + (qy0 * ZQ + qz0) * 4;

    #pragma unroll
    for (int ix = 0; ix < 3; ix++) {
        float w = ex[ix];
        float* b = base + ix * SLAB;
        // element order within quad: e = (ylocal)*2 + (zlocal)
        red4(b,            w*p00, w*p01, w*p10, w*p11);   // quad (gy0,gz0)
        red4(b + 4,        w*p02, w*p03, w*p12, w*p13);   // quad (gy0,gz1)
        red4(b + ZQ*4,     w*p20, w*p21, w*p30, w*p31);   // quad (gy1,gz0)
        red4(b + ZQ*4 + 4, w*p22, w*p23, w*p32, w*p33);   // quad (gy1,gz1)
    }
}

// ---------------------------------------------------------------------------
// Kernel A: [bin blocks first | zero blocks last]. Zero blocks run at the
// kernel tail -> scratch zeros are the freshest L2 lines when splat starts.
// ---------------------------------------------------------------------------
__global__ void __launch_bounds__(256)
bin_zero_kernel(const float* __restrict__ pts,
                const int* __restrict__ mask,
                const int* __restrict__ types)
{
    int g = blockIdx.x;

    if (g >= BIN_BLOCKS) {
        int zid = (g - BIN_BLOCKS) * 256 + threadIdx.x;
        if (zid < SCR_F4)
            ((float4*)g_scr)[zid] = make_float4(0.f, 0.f, 0.f, 0.f);
        return;
    }

    int i = g * 256 + threadIdx.x;
    if (!mask[i]) return;

    float px = pts[3*i + 0];
    float py = pts[3*i + 1];
    float pz = pts[3*i + 2];
    int   t  = types[i];

    int bx = min(max((int)floorf(px * 2.0f), 0), DD - 1);
    int by = min(max((int)floorf(py * 2.0f), 0), DD - 1);
    int bz = min(max((int)floorf(pz * 2.0f), 0), DD - 1);
    int bin = (bx * DD + by) * DD + bz;
    int pos = atomicAdd(&g_count[bin], 1);
    if (pos < STORE_CAP) {
        g_pts[bin * STORE_CAP + pos] =
            make_float4(px, py, pz, __int_as_float((i << 3) | t));
    } else {
        // P ~ 1e-22: park in overflow list; drained in splat_kernel after
        // zeroing is complete (no race with zero blocks).
        int op = atomicAdd(&g_ovf_count, 1);
        if (op < OVF_CAP)
            g_ovf[op] = make_float4(px, py, pz, __int_as_float((i << 3) | t));
    }
}

// ---------------------------------------------------------------------------
// Kernel B: splat (bin = tid/4, slot = tid%4) — 12 uniform red4 per point.
// ---------------------------------------------------------------------------
__global__ void __launch_bounds__(256)
splat_kernel()
{
    int tid = blockIdx.x * 256 + threadIdx.x;
    int bin  = tid >> 2;
    int slot = tid & 3;

    // overflow drain (normally zero entries)
    if (blockIdx.x == 0) {
        int n = min(g_ovf_count, OVF_CAP);
        for (int e = threadIdx.x; e < n; e += 256) {
            float4 r = g_ovf[e];
            splat_point(r.x, r.y, r.z, __float_as_int(r.w) & 7);
        }
    }

    int m = min(g_count[bin], STORE_CAP);
    for (int s = slot; s < m; s += 4) {
        float4 r = g_pts[bin * STORE_CAP + s];
        splat_point(r.x, r.y, r.z, __float_as_int(r.w) & 7);
    }
}

// ---------------------------------------------------------------------------
// transpose: one thread per output 2x2 (y,z) quad. Reads one full quad per
// type (float4), writes 4 cells x 8 types = 128 contiguous bytes.
// NOTE: cell x lives at x-slab (x+1)  (splat stores cell value v at slab v+1).
// ---------------------------------------------------------------------------
__device__ __forceinline__ void do_transpose(int tb, float* __restrict__ lat)
{
    int idx = tb * 256 + threadIdx.x;   // [0, PLANE/4)
    int x   = idx >> 12;                 // 64*64 quads per x-slice
    int rem = idx & 4095;
    int qy  = rem >> 6;
    int qz  = rem & 63;

    // input quad: x-slab = x+1; ypad = 2*qy+2 -> quad qy+1; same for z
    size_t base = (size_t)(x + 1) * SLAB + ((qy + 1) * ZQ + (qz + 1)) * 4;

    float4 v[TT];
    #pragma unroll
    for (int t = 0; t < TT; t++)
        v[t] = *(const float4*)(g_scr + (size_t)t * TPLANE + base);

    int y0 = qy * 2, z0 = qz * 2;
    // element e = (y&1)*2 + (z&1): x->(0,0), y->(0,1), z->(1,0), w->(1,1)
    {
        float4* o = (float4*)(lat + ((size_t)(x * LL + y0) * LL + z0) * TT);
        o[0] = make_float4(v[0].x, v[1].x, v[2].x, v[3].x);
        o[1] = make_float4(v[4].x, v[5].x, v[6].x, v[7].x);
        o[2] = make_float4(v[0].y, v[1].y, v[2].y, v[3].y);
        o[3] = make_float4(v[4].y, v[5].y, v[6].y, v[7].y);
    }
    {
        float4* o = (float4*)(lat + ((size_t)(x * LL + y0 + 1) * LL + z0) * TT);
        o[0] = make_float4(v[0].z, v[1].z, v[2].z, v[3].z);
        o[1] = make_float4(v[4].z, v[5].z, v[6].z, v[7].z);
        o[2] = make_float4(v[0].w, v[1].w, v[2].w, v[3].w);
        o[3] = make_float4(v[4].w, v[5].w, v[6].w, v[7].w);
    }
}

// ---------------------------------------------------------------------------
// fill work for one block (one bin per thread).
// ---------------------------------------------------------------------------
__device__ __forceinline__ void do_fill(int fb,
                                        float* __restrict__ buf,
                                        float* __restrict__ bmask)
{
    int b = fb * 256 + threadIdx.x;

    const float4* rec = &g_pts[(size_t)b * STORE_CAP];

    float w8[CAP];
    #pragma unroll
    for (int e = 0; e < CAP; e++) w8[e] = rec[e].w;

    int cnt = g_count[b];
    int m = min(cnt, STORE_CAP);

    int key[CAP];
    #pragma unroll
    for (int s = 0; s < CAP; s++) key[s] = 0x7FFFFFFF;

    #pragma unroll
    for (int e = 0; e < CAP; e++) {
        if (e >= m) break;
        int k = (__float_as_int(w8[e]) << 5) | e;
        #pragma unroll
        for (int j = 0; j < CAP; j++) {
            int lo = min(k, key[j]);
            int hi = max(k, key[j]);
            key[j] = lo;
            k = hi;
        }
    }
    for (int e = CAP; e < m; e++) {
        int k = (__float_as_int(rec[e].w) << 5) | e;
        #pragma unroll
        for (int j = 0; j < CAP; j++) {
            int lo = min(k, key[j]);
            int hi = max(k, key[j]);
            key[j] = lo;
            k = hi;
        }
    }

    int nval = min(cnt, CAP);
    float o[CAP * 3];
    float mk[CAP];
    #pragma unroll
    for (int s = 0; s < CAP; s++) {
        float x = 0.f, y = 0.f, z = 0.f, mv = 0.f;
        if (s < nval) {
            float4 r = rec[key[s] & (STORE_CAP - 1)];
            x = r.x; y = r.y; z = r.z; mv = 1.0f;
        }
        o[3*s + 0] = x; o[3*s + 1] = y; o[3*s + 2] = z;
        mk[s] = mv;
    }

    float4* bp = (float4*)(buf + (size_t)b * (CAP * 3));
    #pragma unroll
    for (int q = 0; q < 6; q++)
        bp[q] = make_float4(o[4*q + 0], o[4*q + 1], o[4*q + 2], o[4*q + 3]);

    float4* mp = (float4*)(bmask + (size_t)b * CAP);
    mp[0] = make_float4(mk[0], mk[1], mk[2], mk[3]);
    mp[1] = make_float4(mk[4], mk[5], mk[6], mk[7]);
}

// ---------------------------------------------------------------------------
// Kernel C: interleaved [transpose | fill]. Groups of 3: r<2 transpose, r==2 fill.
// ---------------------------------------------------------------------------
__global__ void __launch_bounds__(256)
transpose_fill_kernel(float* __restrict__ lat,
                      float* __restrict__ buf,
                      float* __restrict__ bmask)
{
    int g = blockIdx.x;
    int k = g / 3;
    int r = g - k * 3;
    if (r < 2) do_transpose(k * 2 + r, lat);
    else       do_fill(k, buf, bmask);
}

// ---------------------------------------------------------------------------
extern "C" void kernel_launch(void* const* d_in, const int* in_sizes, int n_in,
                              void* d_out, int out_size)
{
    const float* points = (const float*)d_in[0];
    const int*   mask   = (const int*)d_in[1];
    const int*   types  = (const int*)d_in[2];

    float* out   = (float*)d_out;
    float* lat   = out;                       // [128,128,128,8]
    float* buf   = out + LAT_ELEMS;           // [262144,8,3]
    float* bmask = buf + BUF_ELEMS;           // [262144,8]

    void* cptr = nullptr;
    cudaGetSymbolAddress(&cptr, g_count);
    cudaMemsetAsync(cptr, 0, (size_t)NUM_BINS * sizeof(int), 0);
    void* optr = nullptr;
    cudaGetSymbolAddress(&optr, g_ovf_count);
    cudaMemsetAsync(optr, 0, sizeof(int), 0);

    bin_zero_kernel<<<A_BLOCKS, 256>>>(points, mask, types);
    splat_kernel<<<SPLAT_BLOCKS, 256>>>();
    transpose_fill_kernel<<<C_BLOCKS, 256>>>(lat, buf, bmask);
}